// round 12
// baseline (speedup 1.0000x reference)
#include <cuda_runtime.h>
#include <cuda_bf16.h>
#include <math.h>

// ---------------------------------------------------------------------------
// DeepDCNN: emb-gather -> 4x [grouped conv+fold (writes flipped keys, padded
// rows) -> warp-level ordered top-k + tanh (single global read, smem-resident)]
// -> FC.  B=64, SEQ=1024, E=64, NC=6
// Layer i: Ghalf=[32,16,8,4], CING=[1,10,14,18], NF=[10,14,18,22],
//          KS=[7,5,5,3], SOUT=SIN+KS-1, KPOOL=[768,512,256,4]
// Key-row stride OUTS = SOUT rounded up to 128: [1152, 896, 640, 384];
// pad entries hold key 0 (below every real key; k < #real so never selected).
// ---------------------------------------------------------------------------

__device__ unsigned g_bufA[23592960]; // conv-out keys (max l0: 64*320*1152)
__device__ float    g_bufB[15728640]; // pooled ping (l0: 64*320*768, l2)
__device__ float    g_bufC[7340032];  // embed / pooled pong (l1: 7.34M, l3)

// ---------------------------------------------------------------------------
// 1) Embedding gather + transpose via smem: X[b][e][s] = emb[tokens[b][s]][e]
// ---------------------------------------------------------------------------
__global__ __launch_bounds__(256)
void embed_kernel(const int* __restrict__ tokens,
                  const float* __restrict__ emb,
                  float* __restrict__ X)
{
    __shared__ float sm[64 * 65];
    __shared__ int stok[64];
    int blk = blockIdx.x;            // B * 16 blocks
    int b   = blk >> 4;
    int s0  = (blk & 15) << 6;
    int t   = threadIdx.x;

    if (t < 64) stok[t] = tokens[b * 1024 + s0 + t];
    __syncthreads();

    for (int i = t; i < 64 * 16; i += 256) {
        int r  = i >> 4;
        int c4 = i & 15;
        float4 v = *reinterpret_cast<const float4*>(emb + (long long)stok[r] * 64 + c4 * 4);
        float* d = &sm[r * 65 + c4 * 4];
        d[0] = v.x; d[1] = v.y; d[2] = v.z; d[3] = v.w;
    }
    __syncthreads();

    for (int i = t; i < 64 * 64; i += 256) {
        int e = i >> 6, s = i & 63;
        X[((long long)b * 64 + e) * 1024 + s0 + s] = sm[s * 65 + e];
    }
}

__device__ __forceinline__ unsigned flip_key(float f) {
    unsigned u = __float_as_uint(f);
    return (u & 0x80000000u) ? ~u : (u | 0x80000000u);
}

// ---------------------------------------------------------------------------
// 2) Fused grouped conv + bias + fold, packed f32x2 FMA (R6/R11 core).
//    Writes MONOTONE-FLIPPED keys into padded rows of stride OUTS;
//    positions in [SOUT, OUTS) get key 0. Coverage: stiles*THREADS*SPT >= OUTS.
// ---------------------------------------------------------------------------
template<int CING, int NF, int KS, int THREADS, int SPT>
__global__ __launch_bounds__(THREADS)
void conv_fold_kernel(const float* __restrict__ x, const float* __restrict__ w,
                      const float* __restrict__ bias, unsigned* __restrict__ y,
                      int SIN, int SOUT, int OUTS, int Ghalf, int stiles)
{
    constexpr int TS  = THREADS * SPT;
    constexpr int NFP = NF / 2;
    constexpr int WIN = KS + SPT - 1;
    constexpr int PCN = 2 * CING;
    constexpr int WN  = 2 * NF * CING * KS;
    __shared__ __align__(16) float swT[WN];   // [p][c][j][f]

    int bid  = blockIdx.x;
    int tile = bid % stiles;
    int gp   = (bid / stiles) % Ghalf;
    int b    = bid / (stiles * Ghalf);
    int t    = threadIdx.x;
    int s0   = tile * TS;

    const int CH_IN  = Ghalf * 2 * CING;
    const int CH_OUT = Ghalf * NF;

    const float* wg = w + (long long)(2 * gp) * NF * CING * KS;
    for (int e = t; e < WN; e += THREADS) {
        int j  = e % KS;
        int r  = e / KS;
        int c  = r % CING;
        int r2 = r / CING;
        int f  = r2 % NF;
        int p  = r2 / NF;
        swT[((p * CING + c) * KS + j) * NF + f] = wg[e];
    }
    __syncthreads();

    int sbase = s0 + SPT * t;
    if (sbase >= OUTS) return;

    unsigned* yb = y + (long long)b * CH_OUT * OUTS + (long long)gp * NF * OUTS;

    if (sbase >= SOUT) {             // pure pad-fill thread
        #pragma unroll
        for (int fp = 0; fp < NFP; ++fp) {
            #pragma unroll
            for (int q = 0; q < SPT; ++q) {
                int s = sbase + q;
                if (s < OUTS) {
                    yb[(long long)(2 * fp)     * OUTS + s] = 0u;
                    yb[(long long)(2 * fp + 1) * OUTS + s] = 0u;
                }
            }
        }
        return;
    }

    unsigned long long acc[NFP][SPT];
    #pragma unroll
    for (int fp = 0; fp < NFP; ++fp) {
        float blo = bias[2 * gp * NF + 2 * fp]     + bias[(2 * gp + 1) * NF + 2 * fp];
        float bhi = bias[2 * gp * NF + 2 * fp + 1] + bias[(2 * gp + 1) * NF + 2 * fp + 1];
        unsigned long long pb;
        asm("mov.b64 %0, {%1, %2};" : "=l"(pb)
            : "r"(__float_as_uint(blo)), "r"(__float_as_uint(bhi)));
        #pragma unroll
        for (int q = 0; q < SPT; ++q) acc[fp][q] = pb;
    }

    const float* xb = x + (long long)b * CH_IN * SIN + (long long)(2 * gp * CING) * SIN;
    int gbase = sbase - (KS - 1);

    #pragma unroll 1
    for (int pc = 0; pc < PCN; ++pc) {
        const float* xr = xb + (long long)pc * SIN;
        unsigned long long xd[WIN];
        #pragma unroll
        for (int i = 0; i < WIN; ++i) {
            int g = gbase + i;
            float v = ((unsigned)g < (unsigned)SIN) ? __ldg(&xr[g]) : 0.f;
            asm("mov.b64 %0, {%1, %1};" : "=l"(xd[i]) : "r"(__float_as_uint(v)));
        }
        const float* wrow = &swT[pc * KS * NF];
        #pragma unroll
        for (int j = 0; j < KS; ++j) {
            #pragma unroll
            for (int fp = 0; fp < NFP; ++fp) {
                unsigned long long wp =
                    *reinterpret_cast<const unsigned long long*>(&wrow[j * NF + 2 * fp]);
                #pragma unroll
                for (int q = 0; q < SPT; ++q)
                    asm("fma.rn.f32x2 %0, %1, %2, %0;"
                        : "+l"(acc[fp][q]) : "l"(xd[j + q]), "l"(wp));
            }
        }
    }

    #pragma unroll
    for (int fp = 0; fp < NFP; ++fp) {
        #pragma unroll
        for (int q = 0; q < SPT; ++q) {
            int s = sbase + q;
            if (s < OUTS) {
                unsigned lo, hi;
                asm("mov.b64 {%0, %1}, %2;" : "=r"(lo), "=r"(hi) : "l"(acc[fp][q]));
                unsigned klo = (s < SOUT) ? flip_key(__uint_as_float(lo)) : 0u;
                unsigned khi = (s < SOUT) ? flip_key(__uint_as_float(hi)) : 0u;
                yb[(long long)(2 * fp)     * OUTS + s] = klo;
                yb[(long long)(2 * fp + 1) * OUTS + s] = khi;
            }
        }
    }
}

// ---------------------------------------------------------------------------
// 3) WARP-LEVEL ordered top-k + tanh, smem-resident keys. One warp per row,
//    8 warps/block. Single global read (uint4) caches the row in smem; hist /
//    refinement / final stable compaction all scan smem. Pads (key 0) are
//    never selected (k < #real keys, real keys > 0).
// ---------------------------------------------------------------------------
__device__ __forceinline__ void warp_select_digit(const int* h, int lane, int krem,
                                                  int& dig, int& krem_new, int& bcnt)
{
    int csum = 0;
    int hb_[8];
    #pragma unroll
    for (int j = 0; j < 8; ++j) { hb_[j] = h[lane * 8 + j]; csum += hb_[j]; }
    int S = csum;
    #pragma unroll
    for (int off = 1; off < 32; off <<= 1) {
        int u = __shfl_down_sync(0xFFFFFFFFu, S, off);
        if (lane + off < 32) S += u;
    }
    int ab = S - csum;   // count in bins above my chunk
    int found = -1, kn = 0, bc = 0;
    #pragma unroll
    for (int j = 7; j >= 0; --j) {
        int hb = hb_[j];
        if (found < 0 && ab + hb >= krem && ab < krem) {
            found = lane * 8 + j; kn = krem - ab; bc = hb;
        }
        ab += hb;
    }
    unsigned fb = __ballot_sync(0xFFFFFFFFu, found >= 0);
    int src = __ffs(fb) - 1;
    dig      = __shfl_sync(0xFFFFFFFFu, found, src);
    krem_new = __shfl_sync(0xFFFFFFFFu, kn, src);
    bcnt     = __shfl_sync(0xFFFFFFFFu, bc, src);
}

template<int NP>
__global__ __launch_bounds__(256)
void kmax_warp_kernel(const unsigned* __restrict__ x, float* __restrict__ y,
                      int k, int nrows)
{
    static_assert(NP % 128 == 0, "NP must be a multiple of 128");
    __shared__ __align__(16) unsigned skeys[8][NP];
    __shared__ int hist[8][256];

    int wid  = threadIdx.x >> 5;
    int lane = threadIdx.x & 31;
    int row  = blockIdx.x * 8 + wid;
    if (row >= nrows) return;                 // warp-uniform

    const unsigned* xr = x + (long long)row * NP;
    unsigned* sk = skeys[wid];
    int* h = hist[wid];

    #pragma unroll
    for (int j = 0; j < 8; ++j) h[lane + 32 * j] = 0;
    __syncwarp();

    // ---- pass 1: global -> smem (uint4), top-byte hist ---------------------
    for (int base = 0; base < NP; base += 128) {
        uint4 kv = *reinterpret_cast<const uint4*>(xr + base + lane * 4);
        *reinterpret_cast<uint4*>(&sk[base + lane * 4]) = kv;
        unsigned v[4] = {kv.x, kv.y, kv.z, kv.w};
        #pragma unroll
        for (int j = 0; j < 4; ++j) {
            int d = (int)(v[j] >> 24);
            unsigned m = __match_any_sync(0xFFFFFFFFu, d);
            if (lane == (__ffs(m) - 1)) atomicAdd(&h[d], __popc(m));
        }
    }
    __syncwarp();

    int dig, krem, bcnt;
    warp_select_digit(h, lane, k, dig, krem, bcnt);
    unsigned prefix = (unsigned)dig << 24;
    int done = (bcnt == krem);                // whole bucket kept

    // ---- refinement passes over smem keys ----------------------------------
    for (int shift = 16; shift >= 0; shift -= 8) {
        if (done) break;                      // warp-uniform
        #pragma unroll
        for (int j = 0; j < 8; ++j) h[lane + 32 * j] = 0;
        __syncwarp();
        unsigned hm = 0xFFFFFFFFu << (shift + 8);
        for (int base = 0; base < NP; base += 128) {
            uint4 kv = *reinterpret_cast<uint4*>(&sk[base + lane * 4]);
            unsigned v[4] = {kv.x, kv.y, kv.z, kv.w};
            #pragma unroll
            for (int j = 0; j < 4; ++j) {
                bool ok = ((v[j] & hm) == prefix);
                unsigned ball = __ballot_sync(0xFFFFFFFFu, ok);
                if (ok) {
                    int d = (int)((v[j] >> shift) & 255u);
                    unsigned m = __match_any_sync(ball, d);
                    if (lane == (__ffs(m) - 1)) atomicAdd(&h[d], __popc(m));
                }
            }
        }
        __syncwarp();
        int kn2;
        warp_select_digit(h, lane, krem, dig, kn2, bcnt);
        prefix |= ((unsigned)dig << shift);
        krem = kn2;
        if (bcnt == krem && shift > 0) done = 1;
    }

    const unsigned T = prefix;
    const int need_eq = done ? (NP + 8) : krem;

    // ---- stable compaction + tanh (packed gt/eq shfl-scan) -----------------
    float* yrow = y + (long long)row * k;
    int carry_gt = 0, carry_eq = 0;
    for (int base = 0; base < NP; base += 128) {
        uint4 kv = *reinterpret_cast<uint4*>(&sk[base + lane * 4]);
        unsigned v[4] = {kv.x, kv.y, kv.z, kv.w};
        unsigned gtm = 0, eqm = 0;
        #pragma unroll
        for (int j = 0; j < 4; ++j) {
            if (v[j] > T)  gtm |= (1u << j);
            if (v[j] == T) eqm |= (1u << j);
        }
        int packed = (__popc(gtm) << 8) | __popc(eqm);
        int inc = packed;
        #pragma unroll
        for (int off = 1; off < 32; off <<= 1) {
            int u = __shfl_up_sync(0xFFFFFFFFu, inc, off);
            if (lane >= off) inc += u;
        }
        int excl = inc - packed;
        int tot  = __shfl_sync(0xFFFFFFFFu, inc, 31);
        int lg = carry_gt + (excl >> 8);
        int le = carry_eq + (excl & 0xFF);
        #pragma unroll
        for (int j = 0; j < 4; ++j) {
            bool gt = (gtm >> j) & 1u;
            bool eq = (eqm >> j) & 1u;
            if (gt || (eq && (le + __popc(eqm & ((1u << j) - 1))) < need_eq)) {
                int ggt = lg + __popc(gtm & ((1u << j) - 1));
                int geq = le + __popc(eqm & ((1u << j) - 1));
                int pos = ggt + min(geq, need_eq);
                unsigned key = v[j];
                float f = (key & 0x80000000u) ? __uint_as_float(key & 0x7FFFFFFFu)
                                              : __uint_as_float(~key);
                yrow[pos] = tanhf(f);
            }
        }
        carry_gt += (tot >> 8);
        carry_eq += (tot & 0xFF);
    }
}

// ---------------------------------------------------------------------------
// 4) Final FC: out[b][n] = fcb[n] + sum_i x[b][i] * fcw[n][i],  i < 352
// ---------------------------------------------------------------------------
__global__ void fc_kernel(const float* __restrict__ x, const float* __restrict__ fcw,
                          const float* __restrict__ fcb, float* __restrict__ out)
{
    int t = blockIdx.x * blockDim.x + threadIdx.x;
    if (t >= 64 * 6) return;
    int b = t / 6, n = t % 6;
    const float* xr = x + b * 352;
    const float* wr = fcw + n * 352;
    float acc = fcb[n];
    #pragma unroll 4
    for (int i = 0; i < 352; ++i) acc = fmaf(xr[i], wr[i], acc);
    out[t] = acc;
}

// ---------------------------------------------------------------------------
extern "C" void kernel_launch(void* const* d_in, const int* in_sizes, int n_in,
                              void* d_out, int out_size)
{
    (void)in_sizes; (void)n_in; (void)out_size;
    const int*   tokens = (const int*)  d_in[0];
    const float* emb    = (const float*)d_in[1];
    const float* w1 = (const float*)d_in[2];
    const float* b1 = (const float*)d_in[3];
    const float* w2 = (const float*)d_in[4];
    const float* b2 = (const float*)d_in[5];
    const float* w3 = (const float*)d_in[6];
    const float* b3 = (const float*)d_in[7];
    const float* w4 = (const float*)d_in[8];
    const float* b4 = (const float*)d_in[9];
    const float* fcw = (const float*)d_in[10];
    const float* fcb = (const float*)d_in[11];
    float* out = (float*)d_out;

    unsigned *A;
    float *B_, *C;
    cudaGetSymbolAddress((void**)&A,  g_bufA);
    cudaGetSymbolAddress((void**)&B_, g_bufB);
    cudaGetSymbolAddress((void**)&C,  g_bufC);

    // embed: C = X (64, 64, 1024)
    embed_kernel<<<64 * 16, 256>>>(tokens, emb, C);

    // layer 0: SOUT 1030, OUTS 1152, TS=512, stiles=3 (1536 >= 1152) ; 20480 rows
    conv_fold_kernel<1, 10, 7, 128, 4><<<64 * 32 * 3, 128>>>(C, w1, b1, A, 1024, 1030, 1152, 32, 3);
    kmax_warp_kernel<1152><<<(20480 + 7) / 8, 256>>>(A, B_, 768, 20480);

    // layer 1: SOUT 772, OUTS 896, TS=512, stiles=2 (1024 >= 896) ; 14336 rows
    conv_fold_kernel<10, 14, 5, 128, 4><<<64 * 16 * 2, 128>>>(B_, w2, b2, A, 768, 772, 896, 16, 2);
    kmax_warp_kernel<896><<<(14336 + 7) / 8, 256>>>(A, C, 512, 14336);

    // layer 2: SOUT 516, OUTS 640, TS=512, stiles=2 (1024 >= 640) ; 9216 rows
    conv_fold_kernel<14, 18, 5, 128, 4><<<64 * 8 * 2, 128>>>(C, w3, b3, A, 512, 516, 640, 8, 2);
    kmax_warp_kernel<640><<<(9216 + 7) / 8, 256>>>(A, B_, 256, 9216);

    // layer 3: SOUT 258, OUTS 384, TS=256, stiles=2 (512 >= 384) ; 5632 rows
    conv_fold_kernel<18, 22, 3, 128, 2><<<64 * 4 * 2, 128>>>(B_, w4, b4, A, 256, 258, 384, 4, 2);
    kmax_warp_kernel<384><<<(5632 + 7) / 8, 256>>>(A, C, 4, 5632);

    // fc: (64, 352) @ (6, 352)^T + bias -> (64, 6)
    fc_kernel<<<3, 128>>>(C, fcw, fcb, out);
}

// round 14
// speedup vs baseline: 1.3237x; 1.3237x over previous
#include <cuda_runtime.h>
#include <cuda_bf16.h>
#include <math.h>

// ---------------------------------------------------------------------------
// DeepDCNN: emb-gather -> 4x [grouped conv+fold (writes flipped keys, padded
// rows) -> warp-level ordered top-k + tanh (smem-resident keys)] -> FC.
// B=64, SEQ=1024, E=64, NC=6
// Layer i: Ghalf=[32,16,8,4], CING=[1,10,14,18], NF=[10,14,18,22],
//          KS=[7,5,5,3], SOUT=SIN+KS-1, KPOOL=[768,512,256,4]
// Key-row stride OUTS = SOUT rounded up to 128: [1152, 896, 640, 384];
// pad entries hold key 0 (below every real key; k < #real so never selected).
// ---------------------------------------------------------------------------

__device__ unsigned g_bufA[23592960]; // conv-out keys (max l0: 64*320*1152)
__device__ float    g_bufB[15728640]; // pooled ping (l0: 64*320*768, l2)
__device__ float    g_bufC[7340032];  // embed / pooled pong (l1: 7.34M, l3)

// ---------------------------------------------------------------------------
// 1) Embedding gather + transpose via smem: X[b][e][s] = emb[tokens[b][s]][e]
// ---------------------------------------------------------------------------
__global__ __launch_bounds__(256)
void embed_kernel(const int* __restrict__ tokens,
                  const float* __restrict__ emb,
                  float* __restrict__ X)
{
    __shared__ float sm[64 * 65];
    __shared__ int stok[64];
    int blk = blockIdx.x;            // B * 16 blocks
    int b   = blk >> 4;
    int s0  = (blk & 15) << 6;
    int t   = threadIdx.x;

    if (t < 64) stok[t] = tokens[b * 1024 + s0 + t];
    __syncthreads();

    for (int i = t; i < 64 * 16; i += 256) {
        int r  = i >> 4;
        int c4 = i & 15;
        float4 v = *reinterpret_cast<const float4*>(emb + (long long)stok[r] * 64 + c4 * 4);
        float* d = &sm[r * 65 + c4 * 4];
        d[0] = v.x; d[1] = v.y; d[2] = v.z; d[3] = v.w;
    }
    __syncthreads();

    for (int i = t; i < 64 * 64; i += 256) {
        int e = i >> 6, s = i & 63;
        X[((long long)b * 64 + e) * 1024 + s0 + s] = sm[s * 65 + e];
    }
}

__device__ __forceinline__ unsigned flip_key(float f) {
    unsigned u = __float_as_uint(f);
    return (u & 0x80000000u) ? ~u : (u | 0x80000000u);
}

// ---------------------------------------------------------------------------
// 2) Fused grouped conv + bias + fold, packed f32x2 FMA (unchanged from R12).
//    Writes MONOTONE-FLIPPED keys into padded rows of stride OUTS;
//    positions in [SOUT, OUTS) get key 0. Coverage: stiles*THREADS*SPT >= OUTS.
// ---------------------------------------------------------------------------
template<int CING, int NF, int KS, int THREADS, int SPT>
__global__ __launch_bounds__(THREADS)
void conv_fold_kernel(const float* __restrict__ x, const float* __restrict__ w,
                      const float* __restrict__ bias, unsigned* __restrict__ y,
                      int SIN, int SOUT, int OUTS, int Ghalf, int stiles)
{
    constexpr int TS  = THREADS * SPT;
    constexpr int NFP = NF / 2;
    constexpr int WIN = KS + SPT - 1;
    constexpr int PCN = 2 * CING;
    constexpr int WN  = 2 * NF * CING * KS;
    __shared__ __align__(16) float swT[WN];   // [p][c][j][f]

    int bid  = blockIdx.x;
    int tile = bid % stiles;
    int gp   = (bid / stiles) % Ghalf;
    int b    = bid / (stiles * Ghalf);
    int t    = threadIdx.x;
    int s0   = tile * TS;

    const int CH_IN  = Ghalf * 2 * CING;
    const int CH_OUT = Ghalf * NF;

    const float* wg = w + (long long)(2 * gp) * NF * CING * KS;
    for (int e = t; e < WN; e += THREADS) {
        int j  = e % KS;
        int r  = e / KS;
        int c  = r % CING;
        int r2 = r / CING;
        int f  = r2 % NF;
        int p  = r2 / NF;
        swT[((p * CING + c) * KS + j) * NF + f] = wg[e];
    }
    __syncthreads();

    int sbase = s0 + SPT * t;
    if (sbase >= OUTS) return;

    unsigned* yb = y + (long long)b * CH_OUT * OUTS + (long long)gp * NF * OUTS;

    if (sbase >= SOUT) {             // pure pad-fill thread
        #pragma unroll
        for (int fp = 0; fp < NFP; ++fp) {
            #pragma unroll
            for (int q = 0; q < SPT; ++q) {
                int s = sbase + q;
                if (s < OUTS) {
                    yb[(long long)(2 * fp)     * OUTS + s] = 0u;
                    yb[(long long)(2 * fp + 1) * OUTS + s] = 0u;
                }
            }
        }
        return;
    }

    unsigned long long acc[NFP][SPT];
    #pragma unroll
    for (int fp = 0; fp < NFP; ++fp) {
        float blo = bias[2 * gp * NF + 2 * fp]     + bias[(2 * gp + 1) * NF + 2 * fp];
        float bhi = bias[2 * gp * NF + 2 * fp + 1] + bias[(2 * gp + 1) * NF + 2 * fp + 1];
        unsigned long long pb;
        asm("mov.b64 %0, {%1, %2};" : "=l"(pb)
            : "r"(__float_as_uint(blo)), "r"(__float_as_uint(bhi)));
        #pragma unroll
        for (int q = 0; q < SPT; ++q) acc[fp][q] = pb;
    }

    const float* xb = x + (long long)b * CH_IN * SIN + (long long)(2 * gp * CING) * SIN;
    int gbase = sbase - (KS - 1);

    #pragma unroll 1
    for (int pc = 0; pc < PCN; ++pc) {
        const float* xr = xb + (long long)pc * SIN;
        unsigned long long xd[WIN];
        #pragma unroll
        for (int i = 0; i < WIN; ++i) {
            int g = gbase + i;
            float v = ((unsigned)g < (unsigned)SIN) ? __ldg(&xr[g]) : 0.f;
            asm("mov.b64 %0, {%1, %1};" : "=l"(xd[i]) : "r"(__float_as_uint(v)));
        }
        const float* wrow = &swT[pc * KS * NF];
        #pragma unroll
        for (int j = 0; j < KS; ++j) {
            #pragma unroll
            for (int fp = 0; fp < NFP; ++fp) {
                unsigned long long wp =
                    *reinterpret_cast<const unsigned long long*>(&wrow[j * NF + 2 * fp]);
                #pragma unroll
                for (int q = 0; q < SPT; ++q)
                    asm("fma.rn.f32x2 %0, %1, %2, %0;"
                        : "+l"(acc[fp][q]) : "l"(xd[j + q]), "l"(wp));
            }
        }
    }

    #pragma unroll
    for (int fp = 0; fp < NFP; ++fp) {
        #pragma unroll
        for (int q = 0; q < SPT; ++q) {
            int s = sbase + q;
            if (s < OUTS) {
                unsigned lo, hi;
                asm("mov.b64 {%0, %1}, %2;" : "=r"(lo), "=r"(hi) : "l"(acc[fp][q]));
                unsigned klo = (s < SOUT) ? flip_key(__uint_as_float(lo)) : 0u;
                unsigned khi = (s < SOUT) ? flip_key(__uint_as_float(hi)) : 0u;
                yb[(long long)(2 * fp)     * OUTS + s] = klo;
                yb[(long long)(2 * fp + 1) * OUTS + s] = khi;
            }
        }
    }
}

// ---------------------------------------------------------------------------
// 3) WARP-LEVEL ordered top-k + tanh, smem-resident keys. One warp per row,
//    8 warps/block. DIRECT per-lane atomicAdd histograms (no __match_any —
//    crossbar match throughput was the suspected kmax bottleneck). Final
//    stable compaction via low-latency ballot+popc with lane-strided loads
//    (order-correct). Pads (key 0) never selected (k < #real, real keys > 0).
// ---------------------------------------------------------------------------
__device__ __forceinline__ void warp_select_digit(const int* h, int lane, int krem,
                                                  int& dig, int& krem_new, int& bcnt)
{
    int csum = 0;
    int hb_[8];
    #pragma unroll
    for (int j = 0; j < 8; ++j) { hb_[j] = h[lane * 8 + j]; csum += hb_[j]; }
    int S = csum;
    #pragma unroll
    for (int off = 1; off < 32; off <<= 1) {
        int u = __shfl_down_sync(0xFFFFFFFFu, S, off);
        if (lane + off < 32) S += u;
    }
    int ab = S - csum;   // count in bins above my chunk
    int found = -1, kn = 0, bc = 0;
    #pragma unroll
    for (int j = 7; j >= 0; --j) {
        int hb = hb_[j];
        if (found < 0 && ab + hb >= krem && ab < krem) {
            found = lane * 8 + j; kn = krem - ab; bc = hb;
        }
        ab += hb;
    }
    unsigned fb = __ballot_sync(0xFFFFFFFFu, found >= 0);
    int src = __ffs(fb) - 1;
    dig      = __shfl_sync(0xFFFFFFFFu, found, src);
    krem_new = __shfl_sync(0xFFFFFFFFu, kn, src);
    bcnt     = __shfl_sync(0xFFFFFFFFu, bc, src);
}

template<int NP>
__global__ __launch_bounds__(256)
void kmax_warp_kernel(const unsigned* __restrict__ x, float* __restrict__ y,
                      int k, int nrows)
{
    static_assert(NP % 128 == 0, "NP must be a multiple of 128");
    __shared__ __align__(16) unsigned skeys[8][NP];
    __shared__ int hist[8][256];

    int wid  = threadIdx.x >> 5;
    int lane = threadIdx.x & 31;
    int row  = blockIdx.x * 8 + wid;
    if (row >= nrows) return;                 // warp-uniform

    const unsigned* xr = x + (long long)row * NP;
    unsigned* sk = skeys[wid];
    int* h = hist[wid];

    #pragma unroll
    for (int j = 0; j < 8; ++j) h[lane + 32 * j] = 0;
    __syncwarp();

    // ---- pass 1: global -> smem (uint4), top-byte hist, direct atomics -----
    for (int base = 0; base < NP; base += 128) {
        uint4 kv = *reinterpret_cast<const uint4*>(xr + base + lane * 4);
        *reinterpret_cast<uint4*>(&sk[base + lane * 4]) = kv;
        atomicAdd(&h[kv.x >> 24], 1);
        atomicAdd(&h[kv.y >> 24], 1);
        atomicAdd(&h[kv.z >> 24], 1);
        atomicAdd(&h[kv.w >> 24], 1);
    }
    __syncwarp();

    int dig, krem, bcnt;
    warp_select_digit(h, lane, k, dig, krem, bcnt);
    unsigned prefix = (unsigned)dig << 24;
    int done = (bcnt == krem);                // whole bucket kept

    // ---- refinement passes over smem keys, direct atomics ------------------
    for (int shift = 16; shift >= 0; shift -= 8) {
        if (done) break;                      // warp-uniform
        #pragma unroll
        for (int j = 0; j < 8; ++j) h[lane + 32 * j] = 0;
        __syncwarp();
        unsigned hm = 0xFFFFFFFFu << (shift + 8);
        for (int base = 0; base < NP; base += 128) {
            uint4 kv = *reinterpret_cast<uint4*>(&sk[base + lane * 4]);
            unsigned v[4] = {kv.x, kv.y, kv.z, kv.w};
            #pragma unroll
            for (int j = 0; j < 4; ++j) {
                if ((v[j] & hm) == prefix)
                    atomicAdd(&h[(v[j] >> shift) & 255u], 1);
            }
        }
        __syncwarp();
        int kn2;
        warp_select_digit(h, lane, krem, dig, kn2, bcnt);
        prefix |= ((unsigned)dig << shift);
        krem = kn2;
        if (bcnt == krem && shift > 0) done = 1;
    }

    const unsigned T = prefix;
    const int need_eq = done ? (NP + 8) : krem;

    // ---- stable compaction + tanh (ballot+popc, lane-strided order) --------
    float* yrow = y + (long long)row * k;
    int carry_gt = 0, carry_eq = 0;
    for (int base = 0; base < NP; base += 128) {
        #pragma unroll
        for (int j = 0; j < 4; ++j) {
            unsigned key = sk[base + j * 32 + lane];
            bool gt = key > T;
            bool eq = key == T;
            unsigned bg = __ballot_sync(0xFFFFFFFFu, gt);
            unsigned be = __ballot_sync(0xFFFFFFFFu, eq);
            unsigned ltm = (1u << lane) - 1;
            int ggt = carry_gt + __popc(bg & ltm);
            int geq = carry_eq + __popc(be & ltm);
            if (gt || (eq && geq < need_eq)) {
                int pos = ggt + min(geq, need_eq);
                float f = (key & 0x80000000u) ? __uint_as_float(key & 0x7FFFFFFFu)
                                              : __uint_as_float(~key);
                yrow[pos] = tanhf(f);
            }
            carry_gt += __popc(bg);
            carry_eq += __popc(be);
        }
    }
}

// ---------------------------------------------------------------------------
// 4) Final FC: out[b][n] = fcb[n] + sum_i x[b][i] * fcw[n][i],  i < 352
// ---------------------------------------------------------------------------
__global__ void fc_kernel(const float* __restrict__ x, const float* __restrict__ fcw,
                          const float* __restrict__ fcb, float* __restrict__ out)
{
    int t = blockIdx.x * blockDim.x + threadIdx.x;
    if (t >= 64 * 6) return;
    int b = t / 6, n = t % 6;
    const float* xr = x + b * 352;
    const float* wr = fcw + n * 352;
    float acc = fcb[n];
    #pragma unroll 4
    for (int i = 0; i < 352; ++i) acc = fmaf(xr[i], wr[i], acc);
    out[t] = acc;
}

// ---------------------------------------------------------------------------
extern "C" void kernel_launch(void* const* d_in, const int* in_sizes, int n_in,
                              void* d_out, int out_size)
{
    (void)in_sizes; (void)n_in; (void)out_size;
    const int*   tokens = (const int*)  d_in[0];
    const float* emb    = (const float*)d_in[1];
    const float* w1 = (const float*)d_in[2];
    const float* b1 = (const float*)d_in[3];
    const float* w2 = (const float*)d_in[4];
    const float* b2 = (const float*)d_in[5];
    const float* w3 = (const float*)d_in[6];
    const float* b3 = (const float*)d_in[7];
    const float* w4 = (const float*)d_in[8];
    const float* b4 = (const float*)d_in[9];
    const float* fcw = (const float*)d_in[10];
    const float* fcb = (const float*)d_in[11];
    float* out = (float*)d_out;

    unsigned *A;
    float *B_, *C;
    cudaGetSymbolAddress((void**)&A,  g_bufA);
    cudaGetSymbolAddress((void**)&B_, g_bufB);
    cudaGetSymbolAddress((void**)&C,  g_bufC);

    // embed: C = X (64, 64, 1024)
    embed_kernel<<<64 * 16, 256>>>(tokens, emb, C);

    // layer 0: SOUT 1030, OUTS 1152, TS=512, stiles=3 ; 20480 rows
    conv_fold_kernel<1, 10, 7, 128, 4><<<64 * 32 * 3, 128>>>(C, w1, b1, A, 1024, 1030, 1152, 32, 3);
    kmax_warp_kernel<1152><<<(20480 + 7) / 8, 256>>>(A, B_, 768, 20480);

    // layer 1: SOUT 772, OUTS 896, TS=512, stiles=2 ; 14336 rows
    conv_fold_kernel<10, 14, 5, 128, 4><<<64 * 16 * 2, 128>>>(B_, w2, b2, A, 768, 772, 896, 16, 2);
    kmax_warp_kernel<896><<<(14336 + 7) / 8, 256>>>(A, C, 512, 14336);

    // layer 2: SOUT 516, OUTS 640, TS=512, stiles=2 ; 9216 rows
    conv_fold_kernel<14, 18, 5, 128, 4><<<64 * 8 * 2, 128>>>(C, w3, b3, A, 512, 516, 640, 8, 2);
    kmax_warp_kernel<640><<<(9216 + 7) / 8, 256>>>(A, B_, 256, 9216);

    // layer 3: SOUT 258, OUTS 384, TS=256, stiles=2 ; 5632 rows
    conv_fold_kernel<18, 22, 3, 128, 2><<<64 * 4 * 2, 128>>>(B_, w4, b4, A, 256, 258, 384, 4, 2);
    kmax_warp_kernel<384><<<(5632 + 7) / 8, 256>>>(A, C, 4, 5632);

    // fc: (64, 352) @ (6, 352)^T + bias -> (64, 6)
    fc_kernel<<<3, 128>>>(C, fcw, fcb, out);
}